// round 1
// baseline (speedup 1.0000x reference)
#include <cuda_runtime.h>
#include <cuda_bf16.h>
#include <cstdint>

// ---------------------------------------------------------------------------
// Problem constants
// ---------------------------------------------------------------------------
#define BATCH 128
#define TLEN  4096
#define HID   13
#define G4    52          // 4*HID
#define NSEQ  256         // BATCH * 2 directions

// ---------------------------------------------------------------------------
// Scratch (device globals — no allocation allowed)
// ---------------------------------------------------------------------------
__device__ float g_pre[(size_t)TLEN * NSEQ * G4];     // 218 MB: [t][seq][k][4gates]
__device__ float g_bufA[(size_t)BATCH * TLEN * 26];   // 54.5 MB layer ping
__device__ float g_bufB[(size_t)BATCH * TLEN * 26];   // 54.5 MB layer pong

// ---------------------------------------------------------------------------
// f32x2 packed math helpers (Blackwell FFMA2 path, PTX-only per SASS_QUICKREF)
// ---------------------------------------------------------------------------
__device__ __forceinline__ unsigned long long pk2(float x, float y) {
    unsigned long long r;
    asm("mov.b64 %0, {%1, %2};" : "=l"(r) : "f"(x), "f"(y));
    return r;
}
__device__ __forceinline__ float2 upk2(unsigned long long v) {
    float2 r;
    asm("mov.b64 {%0, %1}, %2;" : "=f"(r.x), "=f"(r.y) : "l"(v));
    return r;
}
__device__ __forceinline__ unsigned long long fma2(unsigned long long a,
                                                   unsigned long long b,
                                                   unsigned long long c) {
    unsigned long long d;
    asm("fma.rn.f32x2 %0, %1, %2, %3;" : "=l"(d) : "l"(a), "l"(b), "l"(c));
    return d;
}
__device__ __forceinline__ unsigned long long add2(unsigned long long a,
                                                   unsigned long long b) {
    unsigned long long d;
    asm("add.rn.f32x2 %0, %1, %2;" : "=l"(d) : "l"(a), "l"(b));
    return d;
}

// Accurate-enough activations built from ex2.approx / rcp.approx (~1-2 ulp)
__device__ __forceinline__ float ex2a(float x) {
    float r; asm("ex2.approx.f32 %0, %1;" : "=f"(r) : "f"(x)); return r;
}
__device__ __forceinline__ float rcpa(float x) {
    float r; asm("rcp.approx.f32 %0, %1;" : "=f"(r) : "f"(x)); return r;
}
__device__ __forceinline__ float sigm(float x) {
    // 1 / (1 + 2^(-x*log2(e)))
    return rcpa(1.0f + ex2a(-1.4426950408889634f * x));
}
__device__ __forceinline__ float tanh_(float x) {
    // 1 - 2 / (1 + 2^(2x*log2(e)))   (stable at both tails)
    return fmaf(-2.0f, rcpa(1.0f + ex2a(2.8853900817779268f * x)), 1.0f);
}

// ---------------------------------------------------------------------------
// Pre kernel: pre[t][seq][k][4] = x[b,t,:] @ W_ih[dir]^T + b_ih + b_hh
// One thread per (seq, t) row (52 outputs). Weights staged in shared as
// f32x2 gate pairs: m = k + 13*s, s=0 -> (i_k, f_k), s=1 -> (g_k, o_k).
// Lanes in a warp cover consecutive t of the same (b, dir) -> coalesced x.
// ---------------------------------------------------------------------------
template<int D>
__global__ void __launch_bounds__(128)
pre_kernel(const float* __restrict__ x,      // [BATCH][TLEN][D]
           const float* __restrict__ w_ih,   // [2][52][D]
           const float* __restrict__ b_ih,   // [2][52]
           const float* __restrict__ b_hh,   // [2][52]
           float* __restrict__ pre)          // [TLEN][NSEQ][52]
{
    __shared__ alignas(16) unsigned long long wp[D * 26];
    __shared__ unsigned long long bp[26];

    const int tid = threadIdx.x;
    const int gid = blockIdx.x * 128 + tid;          // < 2^20
    const int t   = gid & (TLEN - 1);
    const int seq = gid >> 12;                       // block-uniform (128 | 4096)
    const int dir = seq >> 7;
    const int b   = seq & 127;

    const float* W = w_ih + dir * G4 * D;

    for (int idx = tid; idx < D * 26; idx += 128) {
        const int d = idx / 26, m = idx % 26;
        const int k = m % 13, s = m / 13;
        const int j0 = s ? 26 + k : k;
        wp[idx] = pk2(W[j0 * D + d], W[(j0 + 13) * D + d]);
    }
    if (tid < 26) {
        const int k = tid % 13, s = tid / 13;
        const int j0 = s ? 26 + k : k;
        const float* bi = b_ih + dir * G4;
        const float* bh = b_hh + dir * G4;
        bp[tid] = pk2(bi[j0] + bh[j0], bi[j0 + 13] + bh[j0 + 13]);
    }
    __syncthreads();

    // Load x row into registers
    float xr[D];
    const float* xrow = x + ((size_t)b * TLEN + t) * D;
    if (D == 26) {
        const float2* g = (const float2*)xrow;       // 104B rows -> 8B aligned
        float2* xr2 = (float2*)xr;
#pragma unroll
        for (int i = 0; i < 13; i++) xr2[i] = g[i];
    } else {
#pragma unroll
        for (int d = 0; d < D; d++) xr[d] = xrow[d];
    }

    unsigned long long acc[26];
#pragma unroll
    for (int m = 0; m < 26; m++) acc[m] = bp[m];

#pragma unroll
    for (int d = 0; d < D; d++) {
        const unsigned long long x2 = pk2(xr[d], xr[d]);
        const ulonglong2* row = (const ulonglong2*)(wp + d * 26);
#pragma unroll
        for (int mm = 0; mm < 13; mm++) {
            const ulonglong2 w2 = row[mm];           // broadcast LDS.128
            acc[2 * mm]     = fma2(w2.x, x2, acc[2 * mm]);
            acc[2 * mm + 1] = fma2(w2.y, x2, acc[2 * mm + 1]);
        }
    }

    float4* outp = (float4*)(pre + ((size_t)t * NSEQ + seq) * G4);
#pragma unroll
    for (int k = 0; k < 13; k++) {
        const float2 p01 = upk2(acc[k]);         // (i, f)
        const float2 p23 = upk2(acc[13 + k]);    // (g, o)
        outp[k] = make_float4(p01.x, p01.y, p23.x, p23.y);
    }
}

// ---------------------------------------------------------------------------
// Recurrence kernel: one warp per batch. Lanes 0-12 = fwd dir, lanes 16-28 =
// bwd dir; lane k owns hidden element k (all 4 gates, two f32x2 chains).
// h broadcast via width-16 shuffles. Pre tiles prefetched 4 steps deep.
// ---------------------------------------------------------------------------
__global__ void __launch_bounds__(32)
lstm_rec_kernel(const float* __restrict__ pre,   // [TLEN][NSEQ][52]
                const float* __restrict__ w_hh,  // [2][52][13]
                float* __restrict__ out)         // [BATCH][TLEN][26]
{
    const int lane = threadIdx.x;
    const int b    = blockIdx.x;
    const int dir  = lane >> 4;
    const int k    = lane & 15;
    const int kc   = (k < 13) ? k : 12;
    const bool act = (k < 13);

    // Pack recurrent weights: wA[kk] = (W[i_row][kk], W[f_row][kk]),
    //                         wB[kk] = (W[g_row][kk], W[o_row][kk])
    const float* W = w_hh + dir * G4 * HID;
    unsigned long long wA[13], wB[13];
#pragma unroll
    for (int kk = 0; kk < 13; kk++) {
        wA[kk] = pk2(W[kc * HID + kk],        W[(13 + kc) * HID + kk]);
        wB[kk] = pk2(W[(26 + kc) * HID + kk], W[(39 + kc) * HID + kk]);
    }

    const int seq = dir * BATCH + b;

    // pre pointer in float4 units: index = (t*NSEQ + seq)*13 + kc
    const long long stride4 = (dir == 0) ? (long long)(NSEQ * 13)
                                         : -(long long)(NSEQ * 13);
    const float4* pp = (const float4*)pre +
        (((size_t)(dir == 0 ? 0 : TLEN - 1) * NSEQ + seq) * 13 + kc);

    // output pointer: out[(b*TLEN + tt)*26 + dir*13 + k]
    const long long ostride = (dir == 0) ? 26 : -26;
    float* op = out + ((size_t)b * TLEN + (dir == 0 ? 0 : TLEN - 1)) * 26
                    + dir * 13 + k;

    // 4-deep prefetch ring
    float4 buf[4];
#pragma unroll
    for (int j = 0; j < 4; j++) buf[j] = pp[(long long)j * stride4];
    pp += 4 * stride4;

    float h = 0.0f, c = 0.0f;

    for (int i = 0; i < TLEN; i += 4) {
        const bool pf = (i < TLEN - 4);
#pragma unroll
        for (int j = 0; j < 4; j++) {
            const float4 p = buf[j];
            if (pf) buf[j] = pp[(long long)j * stride4];

            // gates: two packed accumulators, each split into 2 partial chains
            unsigned long long a0 = pk2(p.x, p.y);   // (i, f)
            unsigned long long a1 = pk2(p.z, p.w);   // (g, o)
            unsigned long long c0 = 0ull, c1 = 0ull;
#pragma unroll
            for (int kk = 0; kk < 13; kk++) {
                const float hv = __shfl_sync(0xffffffffu, h, kk, 16);
                const unsigned long long h2 = pk2(hv, hv);
                if (kk & 1) { c0 = fma2(wA[kk], h2, c0); c1 = fma2(wB[kk], h2, c1); }
                else        { a0 = fma2(wA[kk], h2, a0); a1 = fma2(wB[kk], h2, a1); }
            }
            a0 = add2(a0, c0);
            a1 = add2(a1, c1);

            const float2 g01 = upk2(a0);
            const float2 g23 = upk2(a1);
            const float si = sigm(g01.x);
            const float sf = sigm(g01.y);
            const float tg = tanh_(g23.x);
            const float so = sigm(g23.y);

            c = fmaf(sf, c, si * tg);
            h = so * tanh_(c);

            if (act) *op = h;
            op += ostride;
        }
        pp += 4 * stride4;
    }
}

// ---------------------------------------------------------------------------
// Launch: 4 layers x (pre GEMM -> recurrence). Layer 0 D=13, layers 1-3 D=26.
// ---------------------------------------------------------------------------
extern "C" void kernel_launch(void* const* d_in, const int* in_sizes, int n_in,
                              void* d_out, int out_size)
{
    const float* x      = (const float*)d_in[0];
    const float* w_ih0  = (const float*)d_in[1];
    const float* w_hh0  = (const float*)d_in[2];
    const float* b_ih0  = (const float*)d_in[3];
    const float* b_hh0  = (const float*)d_in[4];
    const float* w_ihr  = (const float*)d_in[5];  // [3][2][52][26]
    const float* w_hhr  = (const float*)d_in[6];  // [3][2][52][13]
    const float* b_ihr  = (const float*)d_in[7];  // [3][2][52]
    const float* b_hhr  = (const float*)d_in[8];  // [3][2][52]
    float* out = (float*)d_out;

    float *pre, *bufA, *bufB;
    cudaGetSymbolAddress((void**)&pre,  g_pre);
    cudaGetSymbolAddress((void**)&bufA, g_bufA);
    cudaGetSymbolAddress((void**)&bufB, g_bufB);

    const int PRE_BLOCKS = (NSEQ * TLEN) / 128;   // 8192

    // Layer 0 (D = 13)
    pre_kernel<13><<<PRE_BLOCKS, 128>>>(x, w_ih0, b_ih0, b_hh0, pre);
    lstm_rec_kernel<<<BATCH, 32>>>(pre, w_hh0, bufA);

    // Layers 1-3 (D = 26)
    const float* ins[3]  = {bufA, bufB, bufA};
    float*       outs[3] = {bufB, bufA, out};
    for (int l = 0; l < 3; l++) {
        pre_kernel<26><<<PRE_BLOCKS, 128>>>(ins[l],
                                            w_ihr + (size_t)l * 2 * G4 * 26,
                                            b_ihr + (size_t)l * 2 * G4,
                                            b_hhr + (size_t)l * 2 * G4,
                                            pre);
        lstm_rec_kernel<<<BATCH, 32>>>(pre,
                                       w_hhr + (size_t)l * 2 * G4 * HID,
                                       outs[l]);
    }
}